// round 9
// baseline (speedup 1.0000x reference)
#include <cuda_runtime.h>
#include <stdint.h>

// Problem constants
#define BB 16
#define CC 4
#define HH 512
#define WW 1024
#define ROWS (BB * CC * HH)       // 32768
#define NBLK (ROWS / 8)           // 4096 blocks, 8 warps (rows) each
#define BCN  (BB * CC)            // 64 (b,c) groups; 512 rows (warps) per group

// Per-(b,c) accumulators and done-counters, each padded to a 128B line.
// Zero-initialized at module load; the finisher resets them after reading,
// so every graph replay starts clean.
__device__ float    g_acc[BCN][32];    // [bc][0]=err sum, [bc][1]=cnt sum
__device__ unsigned g_done[BCN][32];   // [bc][0]=completed-warp count (-> 512)

// ---------------------------------------------------------------------------
// Kernel 1 (streaming, warp-independent): one warp per row. Argmax over
// W=1024 of cls_true (first-max), gather offsets at that index, mask by
// vertical, then lane 0 fires two relaxed RED.ADDs plus one release-RED on
// the per-group done counter. NO shared memory, NO barriers, NO with-return
// atomics — nothing for any warp to wait on.
// ---------------------------------------------------------------------------
__global__ __launch_bounds__(256) void row_argmax_kernel(
    const float* __restrict__ offset_pred,
    const float* __restrict__ offset_true,
    const float* __restrict__ cls_true,
    const float* __restrict__ vertical_true)
{
    // Release the PDL-dependent finisher as early as possible: once every
    // block has executed this, the secondary grid may launch and start
    // spinning, overlapping its launch + warmup with our last wave.
    if (threadIdx.x == 0) {
        asm volatile("griddepcontrol.launch_dependents;");
    }

    const int warp_in_block = threadIdx.x >> 5;
    const int lane = threadIdx.x & 31;
    const int row = blockIdx.x * 8 + warp_in_block;

    const float4* crow = reinterpret_cast<const float4*>(cls_true + (size_t)row * WW);

    // Front-batch all 8 coalesced float4 loads (512B/warp each) -> MLP 8.
    float4 v[8];
#pragma unroll
    for (int k = 0; k < 8; k++) {
        v[k] = __ldcs(&crow[k * 32 + lane]);   // streaming: read-once data
    }

    // Per-lane scan in increasing index order (first-max within lane).
    float best = -__int_as_float(0x7f800000);  // -inf
    int   bidx = 0;
#pragma unroll
    for (int k = 0; k < 8; k++) {
        const int base = (k * 32 + lane) * 4;
        if (v[k].x > best) { best = v[k].x; bidx = base + 0; }
        if (v[k].y > best) { best = v[k].y; bidx = base + 1; }
        if (v[k].z > best) { best = v[k].z; bidx = base + 2; }
        if (v[k].w > best) { best = v[k].w; bidx = base + 3; }
    }

    // Warp reduction: larger value wins; exact tie -> smaller index (first-max).
#pragma unroll
    for (int off = 16; off > 0; off >>= 1) {
        float oval = __shfl_xor_sync(0xffffffffu, best, off);
        int   oidx = __shfl_xor_sync(0xffffffffu, bidx, off);
        if (oval > best || (oval == best && oidx < bidx)) {
            best = oval;
            bidx = oidx;
        }
    }

    // Lane 0: gather + mask + fire-and-forget accumulation. No waits.
    if (lane == 0) {
        const size_t gidx = (size_t)row * WW + bidx;
        float p = __ldg(&offset_pred[gidx]);
        float t = __ldg(&offset_true[gidx]);
        float mask = (__ldg(&vertical_true[row]) >= 0.5f) ? 1.0f : 0.0f;
        float e = fabsf(p - t) * mask;

        const int bc = row >> 9;               // row / 512
        atomicAdd(&g_acc[bc][0], e);           // REDG.ADD, relaxed
        atomicAdd(&g_acc[bc][1], mask);        // REDG.ADD, relaxed
        // Release-RED: orders the two REDs above before the count bump.
        asm volatile("red.release.gpu.global.add.u32 [%0], 1;"
                     :: "l"(&g_done[bc][0]) : "memory");
    }
}

// ---------------------------------------------------------------------------
// Kernel 2 (finisher, PDL secondary, 1 warp): released early via
// launch_dependents; spins on acquire-loads of the 64 done counters until
// every group reports 512 completed warps, then reduces the 64 L2-hot pairs,
// writes the scalar, and resets all state for the next graph replay.
// ---------------------------------------------------------------------------
__global__ __launch_bounds__(32) void final_reduce_kernel(float* __restrict__ out)
{
    const int lane = threadIdx.x;   // 0..31; lane monitors groups lane, lane+32

    // Spin until all 64 groups are complete.
    for (;;) {
        unsigned a, b;
        asm volatile("ld.acquire.gpu.global.u32 %0, [%1];"
                     : "=r"(a) : "l"(&g_done[lane][0]) : "memory");
        asm volatile("ld.acquire.gpu.global.u32 %0, [%1];"
                     : "=r"(b) : "l"(&g_done[lane + 32][0]) : "memory");
        if (__all_sync(0xffffffffu, (a == 512u) && (b == 512u))) break;
        __nanosleep(128);
    }

    // All release-REDs observed -> accumulators are final.
    float pbc = 0.0f;
#pragma unroll
    for (int g = 0; g < 2; g++) {
        const int bc = g * 32 + lane;
        float ge = __ldcg(&g_acc[bc][0]);
        float gc = __ldcg(&g_acc[bc][1]);
        pbc += (gc > 0.0f) ? (ge / fmaxf(gc, 1.0f)) : 0.0f;
        // Reset for the next replay (visible at kernel boundary).
        g_acc[bc][0] = 0.0f;
        g_acc[bc][1] = 0.0f;
        g_done[bc][0] = 0u;
    }

#pragma unroll
    for (int off = 16; off > 0; off >>= 1) {
        pbc += __shfl_xor_sync(0xffffffffu, pbc, off);
    }
    if (lane == 0) {
        out[0] = pbc / (float)BB;
    }
}

// ---------------------------------------------------------------------------
extern "C" void kernel_launch(void* const* d_in, const int* in_sizes, int n_in,
                              void* d_out, int out_size)
{
    const float* offset_pred   = (const float*)d_in[0];
    const float* offset_true   = (const float*)d_in[1];
    const float* cls_true      = (const float*)d_in[2];
    const float* vertical_true = (const float*)d_in[3];
    float* out = (float*)d_out;

    row_argmax_kernel<<<NBLK, 256>>>(offset_pred, offset_true, cls_true,
                                     vertical_true);

    // PDL: the finisher may launch as soon as every primary block has
    // executed griddepcontrol.launch_dependents (i.e., when the last wave
    // starts), overlapping its node overhead with the primary's drain.
    cudaLaunchAttribute attrs[1];
    attrs[0].id = cudaLaunchAttributeProgrammaticStreamSerialization;
    attrs[0].val.programmaticStreamSerializationAllowed = 1;

    cudaLaunchConfig_t cfg = {};
    cfg.gridDim = dim3(1, 1, 1);
    cfg.blockDim = dim3(32, 1, 1);
    cfg.dynamicSmemBytes = 0;
    cfg.stream = 0;
    cfg.attrs = attrs;
    cfg.numAttrs = 1;

    cudaLaunchKernelEx(&cfg, final_reduce_kernel, out);
}

// round 10
// speedup vs baseline: 1.1644x; 1.1644x over previous
#include <cuda_runtime.h>
#include <stdint.h>

// Problem constants
#define BB 16
#define CC 4
#define HH 512
#define WW 1024
#define ROWS (BB * CC * HH)       // 32768
#define NGRP (ROWS / 8)           // 4096 row-groups of 8 rows
#define BCN  (BB * CC)            // 64 (b,c) groups; 64 row-groups per bc
#define PBLK 1184                 // persistent grid: 148 SMs x 8 CTAs

// Per-(b,c) accumulators, padded to 128B stride to spread across L2 slices.
// [bc][0] = err sum, [bc][1] = cnt sum. Zero-initialized at module load; the
// finisher resets them after reading, so every graph replay sees zeros.
__device__ float g_acc[BCN][32];

// ---------------------------------------------------------------------------
// Kernel 1 (persistent streaming): 1184 blocks of 8 warps; each block loops
// over row-groups g = bid, bid+1184, ... Each warp handles one row per
// iteration: argmax over W=1024 (first-max via parallel max-tree + first-
// matching-index), gather offsets, mask by vertical, warp-local result; the
// block's 8 row results are REDG.ADD'ed (fire-and-forget) per iteration.
// No with-return atomics, no polling — proven-clean stream tail.
// ---------------------------------------------------------------------------
__global__ __launch_bounds__(256) void row_argmax_kernel(
    const float* __restrict__ offset_pred,
    const float* __restrict__ offset_true,
    const float* __restrict__ cls_true,
    const float* __restrict__ vertical_true)
{
    const int warp_in_block = threadIdx.x >> 5;
    const int lane = threadIdx.x & 31;

    for (int g = blockIdx.x; g < NGRP; g += PBLK) {
        const int row = g * 8 + warp_in_block;

        const float4* crow =
            reinterpret_cast<const float4*>(cls_true + (size_t)row * WW);

        // Front-batch 8 coalesced float4 loads (512B/warp each) -> MLP 8.
        float4 v[8];
#pragma unroll
        for (int k = 0; k < 8; k++) {
            v[k] = __ldcs(&crow[k * 32 + lane]);   // streaming: read-once
        }

        // ---- Parallel max over this lane's 32 values (fmaxf tree) ----
        float m[8];
#pragma unroll
        for (int k = 0; k < 8; k++) {
            m[k] = fmaxf(fmaxf(v[k].x, v[k].y), fmaxf(v[k].z, v[k].w));
        }
        float lmax = fmaxf(fmaxf(fmaxf(m[0], m[1]), fmaxf(m[2], m[3])),
                           fmaxf(fmaxf(m[4], m[5]), fmaxf(m[6], m[7])));

        // Warp max (5 butterfly steps).
        float wmax = lmax;
#pragma unroll
        for (int off = 16; off > 0; off >>= 1) {
            wmax = fmaxf(wmax, __shfl_xor_sync(0xffffffffu, wmax, off));
        }

        // ---- First index equal to wmax (min-index tree) ----
        int lidx = 0x7fffffff;
#pragma unroll
        for (int k = 0; k < 8; k++) {
            const int base = (k * 32 + lane) * 4;
            if (v[k].x == wmax) lidx = min(lidx, base + 0);
            if (v[k].y == wmax) lidx = min(lidx, base + 1);
            if (v[k].z == wmax) lidx = min(lidx, base + 2);
            if (v[k].w == wmax) lidx = min(lidx, base + 3);
        }
        int widx = lidx;
#pragma unroll
        for (int off = 16; off > 0; off >>= 1) {
            widx = min(widx, __shfl_xor_sync(0xffffffffu, widx, off));
        }

        // Lane 0: gather + mask + fire-and-forget accumulation.
        if (lane == 0) {
            const size_t gidx = (size_t)row * WW + widx;
            float p = __ldg(&offset_pred[gidx]);
            float t = __ldg(&offset_true[gidx]);
            float mask = (__ldg(&vertical_true[row]) >= 0.5f) ? 1.0f : 0.0f;
            float e = fabsf(p - t) * mask;

            const int bc = row >> 9;            // row / 512
            atomicAdd(&g_acc[bc][0], e);        // REDG.ADD (no return)
            atomicAdd(&g_acc[bc][1], mask);     // REDG.ADD (no return)
        }
    }
}

// ---------------------------------------------------------------------------
// Kernel 2 (finisher, PDL secondary): 64 threads read the 64 accumulator
// pairs (L2-hot), compute per-group means, reduce, write the scalar, and
// reset the accumulators for the next graph replay. Identical to the proven
// R7 finisher.
// ---------------------------------------------------------------------------
__global__ __launch_bounds__(64) void final_reduce_kernel(float* __restrict__ out)
{
#if __CUDA_ARCH__ >= 900
    cudaGridDependencySynchronize();
#endif

    const int t = threadIdx.x;   // 0..63

    float e = g_acc[t][0];
    float c = g_acc[t][1];
    float pbc = (c > 0.0f) ? (e / fmaxf(c, 1.0f)) : 0.0f;

    // Reset for the next replay (visible at kernel boundary).
    g_acc[t][0] = 0.0f;
    g_acc[t][1] = 0.0f;

    // Reduce 64 values across 2 warps.
    __shared__ float s_w[2];
#pragma unroll
    for (int off = 16; off > 0; off >>= 1) {
        pbc += __shfl_xor_sync(0xffffffffu, pbc, off);
    }
    if ((t & 31) == 0) s_w[t >> 5] = pbc;
    __syncthreads();

    if (t == 0) {
        out[0] = (s_w[0] + s_w[1]) / (float)BB;
    }
}

// ---------------------------------------------------------------------------
extern "C" void kernel_launch(void* const* d_in, const int* in_sizes, int n_in,
                              void* d_out, int out_size)
{
    const float* offset_pred   = (const float*)d_in[0];
    const float* offset_true   = (const float*)d_in[1];
    const float* cls_true      = (const float*)d_in[2];
    const float* vertical_true = (const float*)d_in[3];
    float* out = (float*)d_out;

    row_argmax_kernel<<<PBLK, 256>>>(offset_pred, offset_true, cls_true,
                                     vertical_true);

    // PDL finisher (R7-proven): overlaps launch latency with the primary.
    cudaLaunchAttribute attrs[1];
    attrs[0].id = cudaLaunchAttributeProgrammaticStreamSerialization;
    attrs[0].val.programmaticStreamSerializationAllowed = 1;

    cudaLaunchConfig_t cfg = {};
    cfg.gridDim = dim3(1, 1, 1);
    cfg.blockDim = dim3(64, 1, 1);
    cfg.dynamicSmemBytes = 0;
    cfg.stream = 0;
    cfg.attrs = attrs;
    cfg.numAttrs = 1;

    cudaLaunchKernelEx(&cfg, final_reduce_kernel, out);
}